// round 14
// baseline (speedup 1.0000x reference)
#include <cuda_runtime.h>
#include <cuda_bf16.h>
#include <cstdint>

// Problem constants:
//   radar_patches, mde_out_patches: (W, B, C=1, H, 1) float32
//   output: (B, 1, H, W) float32
#define PW 1600
#define PB 4
#define PH 900
#define NCOL (PW * PB)              // 6400 columns, each contiguous H floats
#define NBUCK 128
#define BSCALE (128.0f / 82.0f)     // depths in [1,81]; clamped anyway
#define SAFE_R 0.6f                 // < bucket width 0.640625 -> exactness guaranteed
#define MAXQ 64                     // queries tracked in the 64-bit mask fast path

// 23 MB scratch for column results in (w,b,h) layout (coalesced writes),
// transposed into the (b,h,w) output by a second kernel.
__device__ float g_cols[(size_t)NCOL * PH];

__device__ __forceinline__ int bucket_of(float v) {
    int b = __float2int_rd(v * BSCALE);
    return min(NBUCK - 1, max(0, b));
}

__global__ __launch_bounds__(256) void radar_column_kernel(
    const float* __restrict__ radar,   // (W,B,H) contiguous per column
    const float* __restrict__ mde,     // (W,B,H)
    float* __restrict__ cols)          // (W,B,H) scratch
{
    // fast path state: at most MAXQ=64 queries, tracked by depth-bucket bitmasks.
    // s_best[q] key = (|diff|_bits << 10) | mde_index  (lex-min == argmin w/ first-index tie)
    __shared__ unsigned long long s_mask[NBUCK];   // bit q set if query q in this bucket
    __shared__ unsigned long long s_best[MAXQ];
    __shared__ float          s_entryD[MAXQ];
    __shared__ unsigned short s_entryY[MAXQ];
    __shared__ unsigned short s_bestY[MAXQ];
    __shared__ unsigned char  s_fb[MAXQ];          // fallback query list (rare)
    __shared__ __align__(16) float s_col[PH];
    __shared__ int s_wsum[8];
    __shared__ int s_nvalid, s_nmde, s_nfb;

    const int colId = blockIdx.x;              // w*B + b
    const float* rcol = radar + (size_t)colId * PH;
    const float* mcol = mde   + (size_t)colId * PH;
    const int tid  = threadIdx.x;
    const int lane = tid & 31;
    const int wid  = tid >> 5;

    // ---- init shared state ----
    if (tid < NBUCK) s_mask[tid] = 0ull;
    if (tid < MAXQ)  s_best[tid] = ~0ull;
    for (int i = tid; i < PH; i += 256) s_col[i] = 0.0f;
    if (tid == 0) { s_nfb = 0; s_nmde = 0; }

    // ---- load radar + mde into registers (column base 3600B -> 16B aligned) ----
    const int y0 = tid * 4;
    float r0 = 0.f, r1 = 0.f, r2 = 0.f, r3 = 0.f;
    float m0 = 0.f, m1 = 0.f, m2 = 0.f, m3 = 0.f;
    if (tid < PH / 4) {                        // tid < 225
        float4 r = reinterpret_cast<const float4*>(rcol)[tid];
        float4 m = reinterpret_cast<const float4*>(mcol)[tid];
        r0 = r.x; r1 = r.y; r2 = r.z; r3 = r.w;
        m0 = m.x; m1 = m.y; m2 = m.z; m3 = m.w;
    }
    const int cnt = (r0 != 0.f) + (r1 != 0.f) + (r2 != 0.f) + (r3 != 0.f);
    int mcnt      = (m0 != 0.f) + (m1 != 0.f) + (m2 != 0.f) + (m3 != 0.f);

    // warp inclusive scan of valid-radar counts; warp reduce mde count
    int incl = cnt;
    #pragma unroll
    for (int s = 1; s < 32; s <<= 1) {
        int o = __shfl_up_sync(0xffffffffu, incl, s);
        if (lane >= s) incl += o;
    }
    if (lane == 31) s_wsum[wid] = incl;
    #pragma unroll
    for (int s = 16; s >= 1; s >>= 1) mcnt += __shfl_xor_sync(0xffffffffu, mcnt, s);

    __syncthreads();                                           // bar1

    if (lane == 0) atomicAdd(&s_nmde, mcnt);
    if (tid == 0) {
        int acc = 0;
        #pragma unroll
        for (int w = 0; w < 8; w++) { int c = s_wsum[w]; s_wsum[w] = acc; acc += c; }
        s_nvalid = acc;
    }
    __syncthreads();                                           // bar2

    const int nvalid = s_nvalid;
    const bool fast  = (nvalid <= MAXQ);

    // ---- scatter valid radar entries (ascending y) + set depth-bucket masks ----
    if (fast) {
        int off = s_wsum[wid] + incl - cnt;
        if (r0 != 0.f) { s_entryY[off] = (unsigned short)(y0 + 0); s_entryD[off] = r0; atomicOr(&s_mask[bucket_of(r0)], 1ull << off); off++; }
        if (r1 != 0.f) { s_entryY[off] = (unsigned short)(y0 + 1); s_entryD[off] = r1; atomicOr(&s_mask[bucket_of(r1)], 1ull << off); off++; }
        if (r2 != 0.f) { s_entryY[off] = (unsigned short)(y0 + 2); s_entryD[off] = r2; atomicOr(&s_mask[bucket_of(r2)], 1ull << off); off++; }
        if (r3 != 0.f) { s_entryY[off] = (unsigned short)(y0 + 3); s_entryD[off] = r3; atomicOr(&s_mask[bucket_of(r3)], 1ull << off); off++; }
    }
    __syncthreads();                                           // bar3

    // ---- main pass: each valid mde element updates queries within +-2 depth buckets ----
    if (fast && nvalid > 0) {
        float mv[4] = {m0, m1, m2, m3};
        #pragma unroll
        for (int k = 0; k < 4; k++) {
            float v = mv[k];
            if (v == 0.0f) continue;                           // invalid mde excluded
            int b  = bucket_of(v);
            int lo = max(0, b - 2), hi = min(NBUCK - 1, b + 2);
            unsigned long long m = 0ull;
            for (int bb = lo; bb <= hi; bb++) m |= s_mask[bb];
            while (m) {
                int q = __ffsll((long long)m) - 1;
                m &= m - 1;
                float diff = fabsf(v - s_entryD[q]);
                unsigned long long key =
                    ((unsigned long long)__float_as_uint(diff) << 10) | (unsigned)(y0 + k);
                if (key < s_best[q]) atomicMin(&s_best[q], key);
            }
        }
    }
    __syncthreads();                                           // bar4

    // ---- resolve bestY; collect rare fallbacks ----
    const int nmde = s_nmde;
    if (fast && tid < nvalid) {
        if (nmde == 0) {
            s_bestY[tid] = s_entryY[tid];                      // no valid mde -> own y
        } else {
            unsigned long long k = s_best[tid];
            bool bad = (k == ~0ull) ||
                       (__uint_as_float((unsigned)(k >> 10)) > SAFE_R);
            if (bad) { int p = atomicAdd(&s_nfb, 1); s_fb[p] = (unsigned char)tid; }
            else       s_bestY[tid] = (unsigned short)(k & 1023u);
        }
    }
    __syncthreads();                                           // bar5

    // ---- fallback: exact brute-force argmin (warp per query; essentially never taken) ----
    {
        const int nfb = fast ? s_nfb : 0;
        for (int f = wid; f < nfb; f += 8) {
            const int e = s_fb[f];
            const float d = s_entryD[e];
            unsigned long long bk = ~0ull;
            for (int i = lane; i < PH; i += 32) {
                float v = __ldg(&mcol[i]);
                if (v != 0.0f) {
                    float diff = fabsf(v - d);
                    unsigned long long key =
                        ((unsigned long long)__float_as_uint(diff) << 10) | (unsigned)i;
                    if (key < bk) bk = key;
                }
            }
            #pragma unroll
            for (int s = 16; s >= 1; s >>= 1) {
                unsigned long long o = __shfl_xor_sync(0xffffffffu, bk, s);
                if (o < bk) bk = o;
            }
            if (lane == 0)
                s_bestY[e] = (bk == ~0ull) ? s_entryY[e] : (unsigned short)(bk & 1023u);
        }
    }
    __syncthreads();                                           // bar6

    // ---- sequential placement (exact reference semantics) ----
    if (tid == 0) {
        if (fast) {
            for (int e = 0; e < nvalid; e++) {
                const int   by  = s_bestY[e];
                const float dep = s_entryD[e];
                if (s_col[by] == 0.0f) { s_col[by] = dep; continue; }
                int placed = -1;
                for (int dlt = 1; dlt < PH; dlt++) {
                    int p = by + dlt;
                    if (p < PH && s_col[p] == 0.0f) { placed = p; break; }
                    p = by - dlt;
                    if (p >= 0 && s_col[p] == 0.0f) { placed = p; break; }
                }
                s_col[placed < 0 ? by : placed] = dep;         // all full -> overwrite
            }
        } else {
            // >64 valid radar entries (P ~ 1e-12): run the exact serial reference.
            for (int y = 0; y < PH; y++) {
                float d = rcol[y];
                if (d == 0.0f) continue;
                float bv = __int_as_float(0x7f800000); int bi = -1;
                for (int i = 0; i < PH; i++) {
                    float v = mcol[i];
                    if (v == 0.0f) continue;
                    float df = fabsf(v - d);
                    if (df < bv) { bv = df; bi = i; }
                }
                int by = (bi < 0) ? y : bi;
                if (s_col[by] == 0.0f) { s_col[by] = d; continue; }
                int placed = -1;
                for (int dlt = 1; dlt < PH; dlt++) {
                    int p = by + dlt;
                    if (p < PH && s_col[p] == 0.0f) { placed = p; break; }
                    p = by - dlt;
                    if (p >= 0 && s_col[p] == 0.0f) { placed = p; break; }
                }
                s_col[placed < 0 ? by : placed] = d;
            }
        }
    }
    __syncthreads();                                           // bar7

    // ---- coalesced vectorized write of the column to scratch ----
    if (tid < PH / 4)
        reinterpret_cast<float4*>(cols + (size_t)colId * PH)[tid] =
            reinterpret_cast<const float4*>(s_col)[tid];
}

// cols (W,B,H) -> out (B,1,H,W): 64(w) x 32(h) tiles, float4 in and out
#define TW 64
#define TH 32
__global__ __launch_bounds__(256) void radar_transpose_kernel(
    const float* __restrict__ cols, float* __restrict__ out)
{
    __shared__ __align__(16) float tile[TH][TW + 4];   // pitch 68 floats = 272B (16B-mult)
    const int b     = blockIdx.z;
    const int wBase = blockIdx.x * TW;
    const int hBase = blockIdx.y * TH;
    const int t = threadIdx.x;

    // read: float4 along h (contiguous in cols); scalar STS into transposed tile
    {
        const int wl = t & 63;            // 0..63
        const int hc = t >> 6;            // 0..3
        const float* cbase = cols + ((size_t)(wBase + wl) * PB + b) * PH + hBase;
        #pragma unroll
        for (int it = 0; it < 2; it++) {
            const int h0 = (hc + 4 * it) * 4;     // {0,4,...,28}
            if (hBase + h0 < PH) {                // 900 % 4 == 0: never straddles
                float4 v = *reinterpret_cast<const float4*>(cbase + h0);
                tile[h0 + 0][wl] = v.x;
                tile[h0 + 1][wl] = v.y;
                tile[h0 + 2][wl] = v.z;
                tile[h0 + 3][wl] = v.w;
            }
        }
    }
    __syncthreads();
    // write: float4 along w (contiguous in out)
    {
        const int w4 = (t & 15) * 4;      // 0..60
        const int hl = t >> 4;            // 0..15
        #pragma unroll
        for (int it = 0; it < 2; it++) {
            const int h = hl + 16 * it;
            if (hBase + h < PH) {
                float4 v = *reinterpret_cast<const float4*>(&tile[h][w4]);
                *reinterpret_cast<float4*>(
                    &out[((size_t)b * PH + hBase + h) * PW + wBase + w4]) = v;
            }
        }
    }
}

extern "C" void kernel_launch(void* const* d_in, const int* in_sizes, int n_in,
                              void* d_out, int out_size)
{
    const float* radar = (const float*)d_in[0];   // radar_patches (W,B,1,H,1)
    const float* mde   = (const float*)d_in[1];   // mde_out_patches (W,B,1,H,1)
    float* out = (float*)d_out;                   // (B,1,H,W) float32

    float* cols;
    cudaGetSymbolAddress((void**)&cols, g_cols);

    radar_column_kernel<<<NCOL, 256>>>(radar, mde, cols);

    dim3 tgrid(PW / TW, (PH + TH - 1) / TH, PB);  // 25 x 29 x 4
    radar_transpose_kernel<<<tgrid, 256>>>(cols, out);
}